// round 4
// baseline (speedup 1.0000x reference)
#include <cuda_runtime.h>
#include <math.h>
#include <stdint.h>

#define B_DIM   8
#define HW_DIM  3136
#define C_DIM   256
#define NROWS   (B_DIM * HW_DIM)        // 25088
#define MT      64                      // i/j tile size
#define XPITCH  272                     // [row][k] pitch (floats): conflict-free .128 frags
#define SPITCH  80                      // S pitch: conflict-free .128 frags
#define TPITCH  257                     // T pitch: conflict-free scalar B frags
#define PITCH   68                      // transform kernel smem pitch

// Scratch (device globals — no allocations allowed)
__device__ float g_xn[(size_t)NROWS * C_DIM];   // L2-normalized x
__device__ float g_t [(size_t)NROWS * C_DIM];   // transform branch x@W (fp32 exact)

// fp32 -> tf32 with round-to-nearest (critical: implicit mma truncation is RZ)
__device__ __forceinline__ uint32_t f2tf(float f) {
    uint32_t u;
    asm("cvt.rna.tf32.f32 %0, %1;" : "=r"(u) : "f"(f));
    return u;
}

__device__ __forceinline__ void mma8(float* d, const uint32_t* a,
                                     uint32_t b0, uint32_t b1) {
    asm volatile(
        "mma.sync.aligned.m16n8k8.row.col.f32.tf32.tf32.f32 "
        "{%0,%1,%2,%3}, {%4,%5,%6,%7}, {%8,%9}, {%0,%1,%2,%3};"
        : "+f"(d[0]), "+f"(d[1]), "+f"(d[2]), "+f"(d[3])
        : "r"(a[0]), "r"(a[1]), "r"(a[2]), "r"(a[3]), "r"(b0), "r"(b1));
}

// ---------------------------------------------------------------------------
// Kernel A: row-wise L2 normalize. One warp per row; MUST cover all NROWS rows.
// ---------------------------------------------------------------------------
__global__ void norm_kernel(const float* __restrict__ x) {
    int row  = blockIdx.x * 8 + threadIdx.y;
    int lane = threadIdx.x;
    const float4* xr = reinterpret_cast<const float4*>(x) + (size_t)row * (C_DIM / 4);
    float4 v0 = xr[lane];
    float4 v1 = xr[lane + 32];
    float s = v0.x * v0.x + v0.y * v0.y + v0.z * v0.z + v0.w * v0.w
            + v1.x * v1.x + v1.y * v1.y + v1.z * v1.z + v1.w * v1.w;
#pragma unroll
    for (int off = 16; off > 0; off >>= 1)
        s += __shfl_xor_sync(0xffffffffu, s, off);
    float inv = rsqrtf(fmaxf(s, 1e-12f));
    v0.x *= inv; v0.y *= inv; v0.z *= inv; v0.w *= inv;
    v1.x *= inv; v1.y *= inv; v1.z *= inv; v1.w *= inv;
    float4* o = reinterpret_cast<float4*>(g_xn) + (size_t)row * (C_DIM / 4);
    o[lane]      = v0;
    o[lane + 32] = v1;
}

// ---------------------------------------------------------------------------
// Kernel B: t = x @ W, SIMT fp32 (kept exact so t carries no tf32 error)
// ---------------------------------------------------------------------------
__global__ __launch_bounds__(256)
void transform_kernel(const float* __restrict__ x, const float* __restrict__ W) {
    __shared__ float sXT[64 * PITCH];   // [k][i]
    __shared__ float sWS[64 * PITCH];   // [k][c]

    int row0 = blockIdx.x * 64;
    int c0   = blockIdx.y * 64;
    int tid  = threadIdx.x;
    int tx   = tid & 15, ty = tid >> 4;

    float acc[4][4] = {};

    for (int k0 = 0; k0 < C_DIM; k0 += 64) {
        __syncthreads();
#pragma unroll
        for (int q = 0; q < 16; q++) {
            int idx = tid + q * 256;
            int a   = idx >> 6;
            int bcol = idx & 63;
            sXT[bcol * PITCH + a] = x[(size_t)(row0 + a) * C_DIM + k0 + bcol];
            sWS[a * PITCH + bcol] = W[(size_t)(k0 + a) * C_DIM + c0 + bcol];
        }
        __syncthreads();
#pragma unroll 8
        for (int kk = 0; kk < 64; kk++) {
            float4 av = *reinterpret_cast<const float4*>(&sXT[kk * PITCH + 4 * ty]);
            float4 bv = *reinterpret_cast<const float4*>(&sWS[kk * PITCH + 4 * tx]);
            float aq[4] = {av.x, av.y, av.z, av.w};
            float br[4] = {bv.x, bv.y, bv.z, bv.w};
#pragma unroll
            for (int q = 0; q < 4; q++)
#pragma unroll
                for (int r = 0; r < 4; r++)
                    acc[q][r] += aq[q] * br[r];
        }
    }
#pragma unroll
    for (int q = 0; q < 4; q++) {
        float4 v = make_float4(acc[q][0], acc[q][1], acc[q][2], acc[q][3]);
        *reinterpret_cast<float4*>(
            &g_t[(size_t)(row0 + 4 * ty + q) * C_DIM + c0 + 4 * tx]) = v;
    }
}

// ---------------------------------------------------------------------------
// Kernel C: fused pass on tensor cores (mma.sync tf32).
//   Per CTA (256 thr = 8 warps): 64 i-rows of one batch.
//   Phase 1: S = Xi @ Xj^T  (warp grid 4x2, warp tile 16x32)
//   Phase 2: Y += relu(S)^2 @ T  (warp grid 4x2, warp tile 16x128)
//   k-slot permutation lets all A/B (phase1) fragments load via LDS.128.
// ---------------------------------------------------------------------------
__global__ __launch_bounds__(256)
void ppm_fused(float* __restrict__ y) {
    extern __shared__ uint32_t sm[];
    uint32_t* sXi = sm;                         // [64][XPITCH] tf32 bits
    uint32_t* sXj = sm + MT * XPITCH;           // [64][XPITCH]
    uint32_t* sS  = sm + 2 * MT * XPITCH;       // [64][SPITCH]
    uint32_t* sT  = sXj;                        // alias: [64][TPITCH]

    int b  = blockIdx.y;
    int i0 = blockIdx.x * MT;
    const float* Xb = g_xn + (size_t)b * HW_DIM * C_DIM;
    const float* Tb = g_t  + (size_t)b * HW_DIM * C_DIM;

    int tid  = threadIdx.x;
    int w    = tid >> 5, lane = tid & 31;
    int gid  = lane >> 2, tig = lane & 3;
    int wr   = w & 3;        // 16-row group (both phases)
    int wc   = w >> 2;       // phase1: 32-col group; phase2: 128-col half
    int r1   = 16 * wr + gid;

    // Load Xi tile (tf32-rounded), row-major [i][k]
#pragma unroll
    for (int it = 0; it < 16; it++) {
        int idx = tid + it * 256;           // 0..4095 over 64 rows x 64 float4
        int r = idx >> 6, c4 = (idx & 63) * 4;
        float4 v = *reinterpret_cast<const float4*>(&Xb[(size_t)(i0 + r) * C_DIM + c4]);
        uint4 t;
        t.x = f2tf(v.x); t.y = f2tf(v.y); t.z = f2tf(v.z); t.w = f2tf(v.w);
        *reinterpret_cast<uint4*>(&sXi[r * XPITCH + c4]) = t;
    }

    float yacc[16][4];
#pragma unroll
    for (int nt = 0; nt < 16; nt++)
#pragma unroll
        for (int q = 0; q < 4; q++) yacc[nt][q] = 0.f;

    for (int j0 = 0; j0 < HW_DIM; j0 += MT) {
        __syncthreads();    // prev phase-2 reads of sT done before overwrite

        // Load Xj tile (tf32-rounded)
#pragma unroll
        for (int it = 0; it < 16; it++) {
            int idx = tid + it * 256;
            int r = idx >> 6, c4 = (idx & 63) * 4;
            float4 v = *reinterpret_cast<const float4*>(&Xb[(size_t)(j0 + r) * C_DIM + c4]);
            uint4 t;
            t.x = f2tf(v.x); t.y = f2tf(v.y); t.z = f2tf(v.z); t.w = f2tf(v.w);
            *reinterpret_cast<uint4*>(&sXj[r * XPITCH + c4]) = t;
        }
        __syncthreads();

        // ---- Phase 1: S(16x32 per warp) = Xi @ Xj^T
        float sacc[4][4] = {};
        int p1n0 = 32 * wc;
#pragma unroll
        for (int kb = 0; kb < C_DIM; kb += 32) {
            uint32_t alo0[4], alo1[4], ahi0[4], ahi1[4];
            *(uint4*)alo0 = *(const uint4*)&sXi[r1 * XPITCH + kb + 4 * tig];
            *(uint4*)alo1 = *(const uint4*)&sXi[(r1 + 8) * XPITCH + kb + 4 * tig];
            *(uint4*)ahi0 = *(const uint4*)&sXi[r1 * XPITCH + kb + 16 + 4 * tig];
            *(uint4*)ahi1 = *(const uint4*)&sXi[(r1 + 8) * XPITCH + kb + 16 + 4 * tig];
            uint32_t blo[4][4], bhi[4][4];
#pragma unroll
            for (int nt = 0; nt < 4; nt++) {
                int n = p1n0 + 8 * nt + gid;
                *(uint4*)blo[nt] = *(const uint4*)&sXj[n * XPITCH + kb + 4 * tig];
                *(uint4*)bhi[nt] = *(const uint4*)&sXj[n * XPITCH + kb + 16 + 4 * tig];
            }
#pragma unroll
            for (int s = 0; s < 4; s++) {
                uint32_t afrag[4] = {alo0[s], alo1[s], ahi0[s], ahi1[s]};
#pragma unroll
                for (int nt = 0; nt < 4; nt++)
                    mma8(sacc[nt], afrag, blo[nt][s], bhi[nt][s]);
            }
        }
        // relu^2 -> sS (tf32-rounded)
#pragma unroll
        for (int nt = 0; nt < 4; nt++) {
            int cc = p1n0 + 8 * nt + 2 * tig;
            float v0 = fmaxf(sacc[nt][0], 0.f), v1 = fmaxf(sacc[nt][1], 0.f);
            float v2 = fmaxf(sacc[nt][2], 0.f), v3 = fmaxf(sacc[nt][3], 0.f);
            sS[r1 * SPITCH + cc]           = f2tf(v0 * v0);
            sS[r1 * SPITCH + cc + 1]       = f2tf(v1 * v1);
            sS[(r1 + 8) * SPITCH + cc]     = f2tf(v2 * v2);
            sS[(r1 + 8) * SPITCH + cc + 1] = f2tf(v3 * v3);
        }
        __syncthreads();    // phase-1 reads of sXj done; sS visible

        // Load T tile into aliased buffer (tf32-rounded), pitch 257
#pragma unroll
        for (int it = 0; it < 16; it++) {
            int idx = tid + it * 256;
            int r = idx >> 6, c4 = (idx & 63) * 4;
            float4 v = *reinterpret_cast<const float4*>(&Tb[(size_t)(j0 + r) * C_DIM + c4]);
            uint32_t* d = &sT[r * TPITCH + c4];
            d[0] = f2tf(v.x); d[1] = f2tf(v.y); d[2] = f2tf(v.z); d[3] = f2tf(v.w);
        }
        __syncthreads();

        // ---- Phase 2: Y(16x128 per warp) += S @ T
        int cb = 128 * wc;
#pragma unroll
        for (int kb = 0; kb < MT; kb += 32) {
            uint32_t alo0[4], alo1[4], ahi0[4], ahi1[4];
            *(uint4*)alo0 = *(const uint4*)&sS[r1 * SPITCH + kb + 4 * tig];
            *(uint4*)alo1 = *(const uint4*)&sS[(r1 + 8) * SPITCH + kb + 4 * tig];
            *(uint4*)ahi0 = *(const uint4*)&sS[r1 * SPITCH + kb + 16 + 4 * tig];
            *(uint4*)ahi1 = *(const uint4*)&sS[(r1 + 8) * SPITCH + kb + 16 + 4 * tig];
#pragma unroll
            for (int s = 0; s < 4; s++) {
                uint32_t afrag[4] = {alo0[s], alo1[s], ahi0[s], ahi1[s]};
                const uint32_t* b0row = &sT[(kb + 4 * tig + s) * TPITCH + cb + gid];
                const uint32_t* b1row = &sT[(kb + 16 + 4 * tig + s) * TPITCH + cb + gid];
#pragma unroll
                for (int nt = 0; nt < 16; nt++)
                    mma8(yacc[nt], afrag, b0row[8 * nt], b1row[8 * nt]);
            }
        }
    }

    // Epilogue: write Y (fp32 exact accumulators)
    float* Yb = y + (size_t)b * HW_DIM * C_DIM;
    int orow = i0 + 16 * wr + gid;
#pragma unroll
    for (int nt = 0; nt < 16; nt++) {
        int col = 128 * wc + 8 * nt + 2 * tig;
        *reinterpret_cast<float2*>(&Yb[(size_t)orow * C_DIM + col]) =
            make_float2(yacc[nt][0], yacc[nt][1]);
        *reinterpret_cast<float2*>(&Yb[(size_t)(orow + 8) * C_DIM + col]) =
            make_float2(yacc[nt][2], yacc[nt][3]);
    }
}

// ---------------------------------------------------------------------------
extern "C" void kernel_launch(void* const* d_in, const int* in_sizes, int n_in,
                              void* d_out, int out_size) {
    const float* x = (const float*)d_in[0];   // [8,56,56,256] fp32
    const float* W = (const float*)d_in[1];   // [256,256] fp32
    float* y = (float*)d_out;                 // [8,56,56,256] fp32

    (void)in_sizes; (void)n_in; (void)out_size;

    // A: normalize ALL NROWS = 25088 rows (8 rows per block -> 3136 blocks)
    norm_kernel<<<NROWS / 8, dim3(32, 8)>>>(x);

    transform_kernel<<<dim3(NROWS / 64, C_DIM / 64), 256>>>(x, W);

    size_t shmem = (size_t)(2 * MT * XPITCH + MT * SPITCH) * sizeof(uint32_t); // 159744
    cudaFuncSetAttribute(ppm_fused, cudaFuncAttributeMaxDynamicSharedMemorySize,
                         (int)shmem);
    ppm_fused<<<dim3(HW_DIM / MT, B_DIM), 256, shmem>>>(y);
}

// round 6
// speedup vs baseline: 1.0611x; 1.0611x over previous
#include <cuda_runtime.h>
#include <math.h>
#include <stdint.h>

#define B_DIM   8
#define HW_DIM  3136
#define C_DIM   256
#define NROWS   (B_DIM * HW_DIM)        // 25088
#define PITCH   68                      // transform kernel smem pitch
#define JT      64                      // j tile
#define NJT     (HW_DIM / JT)           // 49

// fused-kernel smem (bytes)
#define SM_XI   0
#define SM_XJ   69632                   // 64 rows x 68 uint4 x 16B
#define SM_TT   139264                  // 16 kq x 258 uint4 x 16B = 66048
#define SM_SS   205312                  // 64 rows x 80 words x 4B = 20480
#define SM_TOT  225792

// device-global scratch, pre-rounded to tf32 bits
__device__ uint32_t g_xn[(size_t)NROWS * C_DIM];            // [row][c]
__device__ uint32_t g_tt[(size_t)B_DIM * C_DIM * HW_DIM];   // [b][c][hw]

__device__ __forceinline__ uint32_t f2tf(float f) {
    uint32_t u; asm("cvt.rna.tf32.f32 %0, %1;" : "=r"(u) : "f"(f)); return u;
}
__device__ __forceinline__ uint32_t smem_u32(const void* p) {
    uint32_t a;
    asm("{ .reg .u64 t; cvta.to.shared.u64 t, %1; cvt.u32.u64 %0, t; }" : "=r"(a) : "l"(p));
    return a;
}
__device__ __forceinline__ void cp16(uint32_t dst, const void* src) {
    asm volatile("{ .reg .u64 g; cvta.to.global.u64 g, %1;"
                 " cp.async.cg.shared.global [%0], [g], 16; }" :: "r"(dst), "l"(src));
}
#define CP_COMMIT() asm volatile("cp.async.commit_group;" ::: "memory")
#define CP_WAIT0()  asm volatile("cp.async.wait_group 0;" ::: "memory")
#define CP_WAIT1()  asm volatile("cp.async.wait_group 1;" ::: "memory")

__device__ __forceinline__ void mma8(float* d, uint32_t a0, uint32_t a1,
                                     uint32_t a2, uint32_t a3,
                                     uint32_t b0, uint32_t b1) {
    asm volatile(
        "mma.sync.aligned.m16n8k8.row.col.f32.tf32.tf32.f32 "
        "{%0,%1,%2,%3}, {%4,%5,%6,%7}, {%8,%9}, {%0,%1,%2,%3};"
        : "+f"(d[0]), "+f"(d[1]), "+f"(d[2]), "+f"(d[3])
        : "r"(a0), "r"(a1), "r"(a2), "r"(a3), "r"(b0), "r"(b1));
}

// ---------------------------------------------------------------------------
// Kernel A: L2 normalize -> g_xn (tf32 bits)
// ---------------------------------------------------------------------------
__global__ void norm_kernel(const float* __restrict__ x) {
    int row  = blockIdx.x * 8 + threadIdx.y;
    int lane = threadIdx.x;
    const float4* xr = reinterpret_cast<const float4*>(x) + (size_t)row * (C_DIM / 4);
    float4 v0 = xr[lane];
    float4 v1 = xr[lane + 32];
    float s = v0.x*v0.x + v0.y*v0.y + v0.z*v0.z + v0.w*v0.w
            + v1.x*v1.x + v1.y*v1.y + v1.z*v1.z + v1.w*v1.w;
#pragma unroll
    for (int off = 16; off > 0; off >>= 1) s += __shfl_xor_sync(0xffffffffu, s, off);
    float inv = rsqrtf(fmaxf(s, 1e-12f));
    uint4 o0 = make_uint4(f2tf(v0.x*inv), f2tf(v0.y*inv), f2tf(v0.z*inv), f2tf(v0.w*inv));
    uint4 o1 = make_uint4(f2tf(v1.x*inv), f2tf(v1.y*inv), f2tf(v1.z*inv), f2tf(v1.w*inv));
    uint4* o = reinterpret_cast<uint4*>(g_xn) + (size_t)row * (C_DIM / 4);
    o[lane] = o0; o[lane + 32] = o1;
}

// ---------------------------------------------------------------------------
// Kernel B: t = x @ W (fp32 exact), stored transposed tf32: g_tt[b][c][hw]
// ---------------------------------------------------------------------------
__global__ __launch_bounds__(256)
void transform_kernel(const float* __restrict__ x, const float* __restrict__ W) {
    __shared__ float sXT[64 * PITCH];
    __shared__ float sWS[64 * PITCH];
    int row0 = blockIdx.x * 64, c0 = blockIdx.y * 64;
    int tid = threadIdx.x, tx = tid & 15, ty = tid >> 4;
    float acc[4][4] = {};
    for (int k0 = 0; k0 < C_DIM; k0 += 64) {
        __syncthreads();
#pragma unroll
        for (int q = 0; q < 16; q++) {
            int idx = tid + q * 256, a = idx >> 6, bc = idx & 63;
            sXT[bc * PITCH + a] = x[(size_t)(row0 + a) * C_DIM + k0 + bc];
            sWS[a * PITCH + bc] = W[(size_t)(k0 + a) * C_DIM + c0 + bc];
        }
        __syncthreads();
#pragma unroll 8
        for (int kk = 0; kk < 64; kk++) {
            float4 av = *reinterpret_cast<const float4*>(&sXT[kk * PITCH + 4 * ty]);
            float4 bv = *reinterpret_cast<const float4*>(&sWS[kk * PITCH + 4 * tx]);
            float aq[4] = {av.x, av.y, av.z, av.w};
            float br[4] = {bv.x, bv.y, bv.z, bv.w};
#pragma unroll
            for (int q = 0; q < 4; q++)
#pragma unroll
                for (int r = 0; r < 4; r++) acc[q][r] += aq[q] * br[r];
        }
    }
    int bb = row0 / HW_DIM, hw0 = row0 - bb * HW_DIM;
#pragma unroll
    for (int q = 0; q < 4; q++)
#pragma unroll
        for (int r = 0; r < 4; r++)
            g_tt[((size_t)bb * C_DIM + c0 + 4 * tx + r) * HW_DIM + hw0 + 4 * ty + q] =
                f2tf(acc[q][r]);
}

// ---------------------------------------------------------------------------
// Kernel C: fused pass, mma.sync tf32, cp.async-overlapped single-buffer pipe.
//   CTA: 256 thr (8 warps), 64 i-rows; per 64-j tile:
//     ph1: S = Xi @ Xj^T   (warp tile 32x16)
//     ph2: Y += relu(S)^2 @ T  (warp tile 32x64; T k-chunked for LDS.128)
// ---------------------------------------------------------------------------
__global__ __launch_bounds__(256)
void ppm_fused(float* __restrict__ y) {
    extern __shared__ char smem[];
    uint32_t sbase = smem_u32(smem);
    const uint4* Xi4 = reinterpret_cast<const uint4*>(smem + SM_XI);
    const uint4* Xj4 = reinterpret_cast<const uint4*>(smem + SM_XJ);
    const uint4* T4  = reinterpret_cast<const uint4*>(smem + SM_TT);
    uint32_t*    sS  = reinterpret_cast<uint32_t*>(smem + SM_SS);
    const uint4* S4  = reinterpret_cast<const uint4*>(smem + SM_SS);

    int b  = blockIdx.y;
    int i0 = blockIdx.x * JT;
    const uint32_t* Xg = g_xn + (size_t)b * HW_DIM * C_DIM;
    const uint32_t* Tg = g_tt + (size_t)b * C_DIM * HW_DIM;

    int tid = threadIdx.x, w = tid >> 5, lane = tid & 31;
    int gid = lane >> 2, tig = lane & 3;
    int wr = w & 1, wn = w >> 1;       // wr: 32-row group; wn: 0..3

    // loaders: 16 cp16 per thread per tile
    auto loadX = [&](int r0, uint32_t dstb) {
#pragma unroll
        for (int q = 0; q < 16; q++) {
            int idx = tid + q * 256, r = idx >> 6, c4 = idx & 63;
            cp16(sbase + dstb + (uint32_t)(r * 68 + c4) * 16,
                 Xg + (size_t)(r0 + r) * C_DIM + c4 * 4);
        }
    };
    auto loadT = [&](int j0) {
#pragma unroll
        for (int q = 0; q < 16; q++) {
            int idx = tid + q * 256, kq = idx >> 8, c = idx & 255;
            cp16(sbase + SM_TT + (uint32_t)(kq * 258 + c) * 16,
                 Tg + (size_t)c * HW_DIM + j0 + kq * 4);
        }
    };

    loadX(i0, SM_XI);
    loadX(0, SM_XJ);
    CP_COMMIT(); CP_WAIT0();
    __syncthreads();

    float yacc[2][8][4];
#pragma unroll
    for (int mb = 0; mb < 2; mb++)
#pragma unroll
        for (int nt = 0; nt < 8; nt++)
#pragma unroll
            for (int q = 0; q < 4; q++) yacc[mb][nt][q] = 0.f;

    for (int j = 0; j < NJT; j++) {
        loadT(j * JT); CP_COMMIT();
        if (j > 0) CP_WAIT1();         // Xj(j) landed
        __syncthreads();

        // ---- phase 1: S(32x16/warp) = Xi @ Xj^T over K=256
        float sacc[2][2][4] = {};
#pragma unroll
        for (int kb4 = 0; kb4 < 64; kb4 += 8) {
            uint4 Aq[2][4];
#pragma unroll
            for (int mb = 0; mb < 2; mb++) {
                int r1 = 32 * wr + 16 * mb + gid;
                Aq[mb][0] = Xi4[r1 * 68 + kb4 + tig];
                Aq[mb][1] = Xi4[(r1 + 8) * 68 + kb4 + tig];
                Aq[mb][2] = Xi4[r1 * 68 + kb4 + 4 + tig];
                Aq[mb][3] = Xi4[(r1 + 8) * 68 + kb4 + 4 + tig];
            }
            uint4 Bq[2][2];
#pragma unroll
            for (int nb = 0; nb < 2; nb++) {
                int n1 = 16 * wn + 8 * nb + gid;
                Bq[nb][0] = Xj4[n1 * 68 + kb4 + tig];
                Bq[nb][1] = Xj4[n1 * 68 + kb4 + 4 + tig];
            }
#pragma unroll
            for (int s = 0; s < 4; s++)
#pragma unroll
                for (int mb = 0; mb < 2; mb++) {
                    const uint32_t* a = reinterpret_cast<const uint32_t*>(&Aq[mb][0]);
#pragma unroll
                    for (int nb = 0; nb < 2; nb++) {
                        const uint32_t* bb = reinterpret_cast<const uint32_t*>(&Bq[nb][0]);
                        mma8(sacc[mb][nb], a[s], a[4 + s], a[8 + s], a[12 + s],
                             bb[s], bb[4 + s]);
                    }
                }
        }
        // relu^2 -> sS (tf32)
#pragma unroll
        for (int mb = 0; mb < 2; mb++)
#pragma unroll
            for (int nb = 0; nb < 2; nb++) {
                int r1 = 32 * wr + 16 * mb + gid;
                int c  = 16 * wn + 8 * nb + 2 * tig;
                float v0 = fmaxf(sacc[mb][nb][0], 0.f), v1 = fmaxf(sacc[mb][nb][1], 0.f);
                float v2 = fmaxf(sacc[mb][nb][2], 0.f), v3 = fmaxf(sacc[mb][nb][3], 0.f);
                *reinterpret_cast<uint2*>(&sS[r1 * 80 + c]) =
                    make_uint2(f2tf(v0 * v0), f2tf(v1 * v1));
                *reinterpret_cast<uint2*>(&sS[(r1 + 8) * 80 + c]) =
                    make_uint2(f2tf(v2 * v2), f2tf(v3 * v3));
            }
        __syncthreads();               // sS ready; sXj free

        if (j + 1 < NJT) { loadX((j + 1) * JT, SM_XJ); CP_COMMIT(); CP_WAIT1(); }
        else CP_WAIT0();               // T(j) landed
        __syncthreads();

        // ---- phase 2: Y(32x64/warp) += S @ T over K=64
#pragma unroll
        for (int kb4 = 0; kb4 < 16; kb4 += 8) {
            uint4 Aq[2][4];
#pragma unroll
            for (int mb = 0; mb < 2; mb++) {
                int r1 = 32 * wr + 16 * mb + gid;
                Aq[mb][0] = S4[r1 * 20 + kb4 + tig];
                Aq[mb][1] = S4[(r1 + 8) * 20 + kb4 + tig];
                Aq[mb][2] = S4[r1 * 20 + kb4 + 4 + tig];
                Aq[mb][3] = S4[(r1 + 8) * 20 + kb4 + 4 + tig];
            }
#pragma unroll
            for (int nt = 0; nt < 8; nt++) {
                int c = 64 * wn + 8 * nt + gid;
                uint4 B0 = T4[(kb4 + tig) * 258 + c];
                uint4 B1 = T4[(kb4 + 4 + tig) * 258 + c];
                const uint32_t* b0 = reinterpret_cast<const uint32_t*>(&B0);
                const uint32_t* b1 = reinterpret_cast<const uint32_t*>(&B1);
#pragma unroll
                for (int s = 0; s < 4; s++)
#pragma unroll
                    for (int mb = 0; mb < 2; mb++) {
                        const uint32_t* a = reinterpret_cast<const uint32_t*>(&Aq[mb][0]);
                        mma8(yacc[mb][nt], a[s], a[4 + s], a[8 + s], a[12 + s],
                             b0[s], b1[s]);
                    }
            }
        }
        __syncthreads();               // ph2 done before next T overwrite
    }

    // epilogue
    float* Yb = y + ((size_t)b * HW_DIM + i0) * C_DIM;
#pragma unroll
    for (int mb = 0; mb < 2; mb++) {
        int r1 = 32 * wr + 16 * mb + gid;
#pragma unroll
        for (int nt = 0; nt < 8; nt++) {
            int c = 64 * wn + 8 * nt + 2 * tig;
            *reinterpret_cast<float2*>(&Yb[(size_t)r1 * C_DIM + c]) =
                make_float2(yacc[mb][nt][0], yacc[mb][nt][1]);
            *reinterpret_cast<float2*>(&Yb[(size_t)(r1 + 8) * C_DIM + c]) =
                make_float2(yacc[mb][nt][2], yacc[mb][nt][3]);
        }
    }
}

// ---------------------------------------------------------------------------
extern "C" void kernel_launch(void* const* d_in, const int* in_sizes, int n_in,
                              void* d_out, int out_size) {
    const float* x = (const float*)d_in[0];
    const float* W = (const float*)d_in[1];
    float* y = (float*)d_out;
    (void)in_sizes; (void)n_in; (void)out_size;

    norm_kernel<<<NROWS / 8, dim3(32, 8)>>>(x);
    transform_kernel<<<dim3(NROWS / 64, C_DIM / 64), 256>>>(x, W);

    cudaFuncSetAttribute(ppm_fused, cudaFuncAttributeMaxDynamicSharedMemorySize, SM_TOT);
    ppm_fused<<<dim3(HW_DIM / JT, B_DIM), 256, SM_TOT>>>(y);
}

// round 8
// speedup vs baseline: 2.4875x; 2.3443x over previous
#include <cuda_runtime.h>
#include <cuda_fp16.h>
#include <math.h>
#include <stdint.h>

#define B_DIM   8
#define HW_DIM  3136
#define C_DIM   256
#define NROWS   (B_DIM * HW_DIM)        // 25088
#define PITCH   68                      // transform kernel smem pitch
#define JT      64                      // j tile
#define NJT     (HW_DIM / JT)           // 49

// fused-kernel smem (bytes). Pitches in uint4 units: X rows 36 (=4 mod 8),
// T/S rows 12 (=4 mod 8) -> conflict-free LDS.128 fragment gathers.
#define XP      36                      // X row pitch (uint4) ; row = 256 halves = 32 u4
#define TP      12                      // T/S row pitch (uint4); row = 64 halves = 8 u4
#define SM_XI   0
#define SM_XJ   36864                   // 64*36*16
#define SM_TT   73728
#define SM_SS   122880                  // T: 256*12*16 = 49152
#define SM_TOT  135168                  // S: 64*12*16 = 12288  -> 122880+12288

// device-global scratch, fp16 (pre-rounded once by producers); 16B-aligned for
// the vectorized cp.async / uint2 paths.
__device__ __align__(16) unsigned short g_xn[(size_t)NROWS * C_DIM];          // [row][c]
__device__ __align__(16) unsigned short g_tt[(size_t)B_DIM * C_DIM * HW_DIM]; // [b][c][hw]

__device__ __forceinline__ uint32_t h2pack(float a, float b) {
    __half2 h = __floats2half2_rn(a, b);      // a -> low half (k), b -> high
    return *reinterpret_cast<uint32_t*>(&h);
}
__device__ __forceinline__ uint32_t smem_u32(const void* p) {
    uint32_t a;
    asm("{ .reg .u64 t; cvta.to.shared.u64 t, %1; cvt.u32.u64 %0, t; }" : "=r"(a) : "l"(p));
    return a;
}
__device__ __forceinline__ void cp16(uint32_t dst, const void* src) {
    asm volatile("{ .reg .u64 g; cvta.to.global.u64 g, %1;"
                 " cp.async.cg.shared.global [%0], [g], 16; }" :: "r"(dst), "l"(src));
}
#define CP_COMMIT() asm volatile("cp.async.commit_group;" ::: "memory")
#define CP_WAIT0()  asm volatile("cp.async.wait_group 0;" ::: "memory")
#define CP_WAIT1()  asm volatile("cp.async.wait_group 1;" ::: "memory")

// fp16 mma, fp32 accum: 2048 FMA per instruction
__device__ __forceinline__ void mma16(float* d, uint32_t a0, uint32_t a1,
                                      uint32_t a2, uint32_t a3,
                                      uint32_t b0, uint32_t b1) {
    asm volatile(
        "mma.sync.aligned.m16n8k16.row.col.f32.f16.f16.f32 "
        "{%0,%1,%2,%3}, {%4,%5,%6,%7}, {%8,%9}, {%0,%1,%2,%3};"
        : "+f"(d[0]), "+f"(d[1]), "+f"(d[2]), "+f"(d[3])
        : "r"(a0), "r"(a1), "r"(a2), "r"(a3), "r"(b0), "r"(b1));
}

// ---------------------------------------------------------------------------
// Kernel A: L2 normalize -> g_xn (fp16)
// ---------------------------------------------------------------------------
__global__ void norm_kernel(const float* __restrict__ x) {
    int row  = blockIdx.x * 8 + threadIdx.y;
    int lane = threadIdx.x;
    const float4* xr = reinterpret_cast<const float4*>(x) + (size_t)row * (C_DIM / 4);
    float4 v0 = xr[lane];
    float4 v1 = xr[lane + 32];
    float s = v0.x*v0.x + v0.y*v0.y + v0.z*v0.z + v0.w*v0.w
            + v1.x*v1.x + v1.y*v1.y + v1.z*v1.z + v1.w*v1.w;
#pragma unroll
    for (int off = 16; off > 0; off >>= 1) s += __shfl_xor_sync(0xffffffffu, s, off);
    float inv = rsqrtf(fmaxf(s, 1e-12f));
    uint2 o0 = make_uint2(h2pack(v0.x*inv, v0.y*inv), h2pack(v0.z*inv, v0.w*inv));
    uint2 o1 = make_uint2(h2pack(v1.x*inv, v1.y*inv), h2pack(v1.z*inv, v1.w*inv));
    uint2* o = reinterpret_cast<uint2*>(g_xn) + (size_t)row * (C_DIM / 4);
    o[lane] = o0; o[lane + 32] = o1;
}

// ---------------------------------------------------------------------------
// Kernel B: t = x @ W (fp32 exact), stored transposed fp16: g_tt[b][c][hw]
// ---------------------------------------------------------------------------
__global__ __launch_bounds__(256)
void transform_kernel(const float* __restrict__ x, const float* __restrict__ W) {
    __shared__ float sXT[64 * PITCH];
    __shared__ float sWS[64 * PITCH];
    int row0 = blockIdx.x * 64, c0 = blockIdx.y * 64;
    int tid = threadIdx.x, tx = tid & 15, ty = tid >> 4;
    float acc[4][4] = {};
    for (int k0 = 0; k0 < C_DIM; k0 += 64) {
        __syncthreads();
#pragma unroll
        for (int q = 0; q < 16; q++) {
            int idx = tid + q * 256, a = idx >> 6, bc = idx & 63;
            sXT[bc * PITCH + a] = x[(size_t)(row0 + a) * C_DIM + k0 + bc];
            sWS[a * PITCH + bc] = W[(size_t)(k0 + a) * C_DIM + c0 + bc];
        }
        __syncthreads();
#pragma unroll 8
        for (int kk = 0; kk < 64; kk++) {
            float4 av = *reinterpret_cast<const float4*>(&sXT[kk * PITCH + 4 * ty]);
            float4 bv = *reinterpret_cast<const float4*>(&sWS[kk * PITCH + 4 * tx]);
            float aq[4] = {av.x, av.y, av.z, av.w};
            float br[4] = {bv.x, bv.y, bv.z, bv.w};
#pragma unroll
            for (int q = 0; q < 4; q++)
#pragma unroll
                for (int r = 0; r < 4; r++) acc[q][r] += aq[q] * br[r];
        }
    }
    int bb = row0 / HW_DIM, hw0 = row0 - bb * HW_DIM;
    // store half2 along the hw dim (acc[q][r], acc[q+1][r] are hw-adjacent)
#pragma unroll
    for (int r = 0; r < 4; r++)
#pragma unroll
        for (int qp = 0; qp < 2; qp++) {
            size_t hidx = ((size_t)bb * C_DIM + c0 + 4 * tx + r) * HW_DIM
                        + hw0 + 4 * ty + 2 * qp;
            *reinterpret_cast<uint32_t*>(&g_tt[hidx]) =
                h2pack(acc[2 * qp][r], acc[2 * qp + 1][r]);
        }
}

// ---------------------------------------------------------------------------
// Kernel C: fused pass, mma.sync fp16 m16n8k16, cp.async-overlapped pipe.
//   CTA: 256 thr (8 warps), 64 i-rows; per 64-j tile:
//     ph1: S = Xi @ Xj^T        (warp tile 32x16, K=256)
//     ph2: Y += relu(S)^2 @ T   (warp tile 32x64, K=64)
// ---------------------------------------------------------------------------
__global__ __launch_bounds__(256)
void ppm_fused(float* __restrict__ y) {
    extern __shared__ char smem[];
    uint32_t sbase = smem_u32(smem);
    const uint4* Xi4 = reinterpret_cast<const uint4*>(smem + SM_XI);
    const uint4* Xj4 = reinterpret_cast<const uint4*>(smem + SM_XJ);
    const uint4* T4  = reinterpret_cast<const uint4*>(smem + SM_TT);
    uint32_t*    sS  = reinterpret_cast<uint32_t*>(smem + SM_SS);   // half2 words
    const uint4* S4  = reinterpret_cast<const uint4*>(smem + SM_SS);

    int b  = blockIdx.y;
    int i0 = blockIdx.x * JT;
    const unsigned short* Xg = g_xn + (size_t)b * HW_DIM * C_DIM;
    const unsigned short* Tg = g_tt + (size_t)b * C_DIM * HW_DIM;

    int tid = threadIdx.x, w = tid >> 5, lane = tid & 31;
    int gid = lane >> 2, tig = lane & 3;
    int wr = w & 1, wn = w >> 1;       // wr: 32-row group; wn: 0..3

    // loaders: 8 cp16 per thread per tile (32KB each)
    auto loadX = [&](int r0, uint32_t dstb) {
#pragma unroll
        for (int q = 0; q < 8; q++) {
            int idx = tid + q * 256, r = idx >> 5, c4 = idx & 31;
            cp16(sbase + dstb + (uint32_t)(r * XP + c4) * 16,
                 Xg + (size_t)(r0 + r) * C_DIM + c4 * 8);
        }
    };
    auto loadT = [&](int j0) {
#pragma unroll
        for (int q = 0; q < 8; q++) {
            int idx = tid + q * 256, c = idx >> 3, k4 = idx & 7;
            cp16(sbase + SM_TT + (uint32_t)(c * TP + k4) * 16,
                 Tg + (size_t)c * HW_DIM + j0 + k4 * 8);
        }
    };

    loadX(i0, SM_XI);
    loadX(0, SM_XJ);
    CP_COMMIT(); CP_WAIT0();
    __syncthreads();

    float yacc[2][8][4];
#pragma unroll
    for (int mb = 0; mb < 2; mb++)
#pragma unroll
        for (int nt = 0; nt < 8; nt++)
#pragma unroll
            for (int q = 0; q < 4; q++) yacc[mb][nt][q] = 0.f;

    for (int j = 0; j < NJT; j++) {
        loadT(j * JT); CP_COMMIT();
        if (j > 0) CP_WAIT1();         // Xj(j) landed
        __syncthreads();

        // ---- phase 1: S(32x16/warp) = Xi @ Xj^T over K=256 (8 chunks of 32)
        float sacc[2][2][4] = {};
#pragma unroll
        for (int kc = 0; kc < 8; kc++) {
            uint4 Ag[2], Ag8[2];
#pragma unroll
            for (int mb = 0; mb < 2; mb++) {
                int r1 = 32 * wr + 16 * mb + gid;
                Ag[mb]  = Xi4[r1 * XP + 4 * kc + tig];
                Ag8[mb] = Xi4[(r1 + 8) * XP + 4 * kc + tig];
            }
            uint4 Bn[2];
#pragma unroll
            for (int nb = 0; nb < 2; nb++) {
                int n1 = 16 * wn + 8 * nb + gid;
                Bn[nb] = Xj4[n1 * XP + 4 * kc + tig];
            }
#pragma unroll
            for (int s = 0; s < 2; s++)
#pragma unroll
                for (int mb = 0; mb < 2; mb++) {
                    const uint32_t* ag  = reinterpret_cast<const uint32_t*>(&Ag[mb]);
                    const uint32_t* ag8 = reinterpret_cast<const uint32_t*>(&Ag8[mb]);
#pragma unroll
                    for (int nb = 0; nb < 2; nb++) {
                        const uint32_t* bn = reinterpret_cast<const uint32_t*>(&Bn[nb]);
                        mma16(sacc[mb][nb], ag[2*s], ag8[2*s], ag[2*s+1], ag8[2*s+1],
                              bn[2*s], bn[2*s+1]);
                    }
                }
        }
        // relu^2 -> sS (fp16, half2 stores; S row pitch = TP*4 = 48 words)
#pragma unroll
        for (int mb = 0; mb < 2; mb++)
#pragma unroll
            for (int nb = 0; nb < 2; nb++) {
                int r1 = 32 * wr + 16 * mb + gid;
                int cw = 8 * wn + 4 * nb + tig;       // half2 col index
                float v0 = fmaxf(sacc[mb][nb][0], 0.f), v1 = fmaxf(sacc[mb][nb][1], 0.f);
                float v2 = fmaxf(sacc[mb][nb][2], 0.f), v3 = fmaxf(sacc[mb][nb][3], 0.f);
                sS[r1 * (TP * 4) + cw]       = h2pack(v0 * v0, v1 * v1);
                sS[(r1 + 8) * (TP * 4) + cw] = h2pack(v2 * v2, v3 * v3);
            }
        __syncthreads();               // sS ready; sXj free

        if (j + 1 < NJT) { loadX((j + 1) * JT, SM_XJ); CP_COMMIT(); CP_WAIT1(); }
        else CP_WAIT0();               // T(j) landed
        __syncthreads();

        // ---- phase 2: Y(32x64/warp) += S @ T over K=64 (2 chunks of 32)
#pragma unroll
        for (int kc = 0; kc < 2; kc++) {
            uint4 Ag[2], Ag8[2];
#pragma unroll
            for (int mb = 0; mb < 2; mb++) {
                int r1 = 32 * wr + 16 * mb + gid;
                Ag[mb]  = S4[r1 * TP + 4 * kc + tig];
                Ag8[mb] = S4[(r1 + 8) * TP + 4 * kc + tig];
            }
#pragma unroll
            for (int nt = 0; nt < 8; nt++) {
                int c = 64 * wn + 8 * nt + gid;
                uint4 Bv = T4[c * TP + 4 * kc + tig];
                const uint32_t* bn = reinterpret_cast<const uint32_t*>(&Bv);
#pragma unroll
                for (int s = 0; s < 2; s++)
#pragma unroll
                    for (int mb = 0; mb < 2; mb++) {
                        const uint32_t* ag  = reinterpret_cast<const uint32_t*>(&Ag[mb]);
                        const uint32_t* ag8 = reinterpret_cast<const uint32_t*>(&Ag8[mb]);
                        mma16(yacc[mb][nt], ag[2*s], ag8[2*s], ag[2*s+1], ag8[2*s+1],
                              bn[2*s], bn[2*s+1]);
                    }
            }
        }
        __syncthreads();               // ph2 done before next T overwrite
    }

    // epilogue (fp32 accumulators -> output)
    float* Yb = y + ((size_t)b * HW_DIM + i0) * C_DIM;
#pragma unroll
    for (int mb = 0; mb < 2; mb++) {
        int r1 = 32 * wr + 16 * mb + gid;
#pragma unroll
        for (int nt = 0; nt < 8; nt++) {
            int c = 64 * wn + 8 * nt + 2 * tig;
            *reinterpret_cast<float2*>(&Yb[(size_t)r1 * C_DIM + c]) =
                make_float2(yacc[mb][nt][0], yacc[mb][nt][1]);
            *reinterpret_cast<float2*>(&Yb[(size_t)(r1 + 8) * C_DIM + c]) =
                make_float2(yacc[mb][nt][2], yacc[mb][nt][3]);
        }
    }
}

// ---------------------------------------------------------------------------
extern "C" void kernel_launch(void* const* d_in, const int* in_sizes, int n_in,
                              void* d_out, int out_size) {
    const float* x = (const float*)d_in[0];
    const float* W = (const float*)d_in[1];
    float* y = (float*)d_out;
    (void)in_sizes; (void)n_in; (void)out_size;

    norm_kernel<<<NROWS / 8, dim3(32, 8)>>>(x);
    transform_kernel<<<dim3(NROWS / 64, C_DIM / 64), 256>>>(x, W);

    cudaFuncSetAttribute(ppm_fused, cudaFuncAttributeMaxDynamicSharedMemorySize, SM_TOT);
    ppm_fused<<<dim3(HW_DIM / JT, B_DIM), 256, SM_TOT>>>(y);
}